// round 1
// baseline (speedup 1.0000x reference)
#include <cuda_runtime.h>
#include <cmath>

#define NN 50000
#define EE 800000
#define EF 850000          // EE + NN self loops
#define ND (NN*64)

// ---------------- scratch (device globals; no allocation) ----------------
__device__ int   g_deg[NN];
__device__ int   g_rowptr[NN+1];
__device__ int   g_cursor[NN];
__device__ int   g_csr_src[EF];     // src node per CSR slot
__device__ int   g_csr_tsrc[EF];    // etype*NN + src per CSR slot
__device__ float g_el[ND];
__device__ float g_er[ND];
__device__ float g_trans[2*ND];
__device__ float g_agg[ND];

// ---------------- packed f32x2 helpers ----------------
__device__ __forceinline__ unsigned long long pk2(float x) {
    unsigned long long r;
    asm("mov.b64 %0, {%1, %1};" : "=l"(r) : "r"(__float_as_uint(x)));
    return r;
}
__device__ __forceinline__ float2 up2(unsigned long long v) {
    float2 f;
    asm("mov.b64 {%0, %1}, %2;" : "=f"(f.x), "=f"(f.y) : "l"(v));
    return f;
}
#define FFMA2(c,a,b) asm("fma.rn.f32x2 %0, %1, %2, %0;" : "+l"(c) : "l"(a), "l"(b))

// ---------------- CSR build ----------------
__global__ void k_zero() {
    int i = blockIdx.x*blockDim.x + threadIdx.x;
    if (i < NN) g_deg[i] = 0;
}
__global__ void k_deg(const int* __restrict__ dst) {
    int e = blockIdx.x*blockDim.x + threadIdx.x;
    if (e >= EF) return;
    int d = (e < EE) ? dst[e] : (e - EE);
    atomicAdd(&g_deg[d], 1);
}
__global__ void k_scan() {
    __shared__ int part[1024];
    int t = threadIdx.x;
    const int CH = (NN + 1023) / 1024;   // 49
    int base = t * CH;
    int s = 0;
    for (int i = 0; i < CH; i++) { int idx = base + i; if (idx < NN) s += g_deg[idx]; }
    part[t] = s; __syncthreads();
    for (int off = 1; off < 1024; off <<= 1) {
        int v = (t >= off) ? part[t - off] : 0;
        __syncthreads();
        part[t] += v;
        __syncthreads();
    }
    int run = (t == 0) ? 0 : part[t-1];
    for (int i = 0; i < CH; i++) {
        int idx = base + i;
        if (idx < NN) { g_rowptr[idx] = run; g_cursor[idx] = run; run += g_deg[idx]; }
    }
    if (t == 1023) g_rowptr[NN] = run;
}
__global__ void k_fill(const int* __restrict__ src, const int* __restrict__ dst,
                       const int* __restrict__ ety) {
    int e = blockIdx.x*blockDim.x + threadIdx.x;
    if (e >= EF) return;
    int s = (e < EE) ? src[e] : (e - EE);
    int d = (e < EE) ? dst[e] : (e - EE);
    int t = ety[e];
    int pos = atomicAdd(&g_cursor[d], 1);
    g_csr_src[pos]  = s;
    g_csr_tsrc[pos] = t*NN + s;
}

// ---------------- dual GEMM: C0 = A@W0^T+b0, C1 = A@W1^T+b1 (64x64 each) ----------------
// block = 64 rows, 256 threads, f32x2 inner product, weights+tile in dyn smem (50KB)
__global__ __launch_bounds__(256) void gemm_dual(
    const float* __restrict__ A,
    const float* __restrict__ W0, const float* __restrict__ b0,
    const float* __restrict__ W1, const float* __restrict__ b1,
    float* __restrict__ C0, float* __restrict__ C1, int n)
{
    extern __shared__ float sm[];
    float* Xs = sm;             // [64][68]  Xs[d][m]
    float* Ws = sm + 64*68;     // [64][132] Ws[d][o], o in [0,128)
    int tid = threadIdx.x;
    int m0 = blockIdx.x * 64;
    #pragma unroll
    for (int k = 0; k < 16; k++) {
        int idx = tid + k*256; int m = idx >> 6, d = idx & 63; int row = m0 + m;
        Xs[d*68 + m] = (row < n) ? A[row*64 + d] : 0.f;
    }
    #pragma unroll
    for (int k = 0; k < 32; k++) {
        int idx = tid + k*256; int o = idx >> 6, d = idx & 63;
        Ws[d*132 + o] = (o < 64) ? W0[o*64 + d] : W1[(o-64)*64 + d];
    }
    __syncthreads();
    int ty = tid >> 4, tx = tid & 15;
    unsigned long long acc[4][4];
    #pragma unroll
    for (int i = 0; i < 4; i++)
        #pragma unroll
        for (int p = 0; p < 4; p++) acc[i][p] = 0ull;

    #pragma unroll 8
    for (int d = 0; d < 64; d++) {
        float4 av = *reinterpret_cast<const float4*>(&Xs[d*68 + ty*4]);
        ulonglong2 bA = *reinterpret_cast<const ulonglong2*>(&Ws[d*132 + tx*8]);
        ulonglong2 bB = *reinterpret_cast<const ulonglong2*>(&Ws[d*132 + tx*8 + 4]);
        unsigned long long a0 = pk2(av.x), a1 = pk2(av.y), a2 = pk2(av.z), a3 = pk2(av.w);
        FFMA2(acc[0][0],a0,bA.x); FFMA2(acc[0][1],a0,bA.y); FFMA2(acc[0][2],a0,bB.x); FFMA2(acc[0][3],a0,bB.y);
        FFMA2(acc[1][0],a1,bA.x); FFMA2(acc[1][1],a1,bA.y); FFMA2(acc[1][2],a1,bB.x); FFMA2(acc[1][3],a1,bB.y);
        FFMA2(acc[2][0],a2,bA.x); FFMA2(acc[2][1],a2,bA.y); FFMA2(acc[2][2],a2,bB.x); FFMA2(acc[2][3],a2,bB.y);
        FFMA2(acc[3][0],a3,bA.x); FFMA2(acc[3][1],a3,bA.y); FFMA2(acc[3][2],a3,bB.x); FFMA2(acc[3][3],a3,bB.y);
    }
    const float* bb; float* Cb; int ob = tx*8;
    if (tx < 8) { Cb = C0; bb = b0; } else { Cb = C1; bb = b1; ob -= 64; }
    #pragma unroll
    for (int i = 0; i < 4; i++) {
        int row = m0 + ty*4 + i;
        if (row >= n) continue;
        #pragma unroll
        for (int p = 0; p < 4; p++) {
            float2 v = up2(acc[i][p]);
            int o = ob + 2*p;
            v.x += bb[o]; v.y += bb[o+1];
            *reinterpret_cast<float2*>(&Cb[row*64 + o]) = v;
        }
    }
}

// ---------------- fused GATv2 edge-softmax + aggregation (online softmax) ----------------
__global__ void k_gat(const float* __restrict__ attn,
                      float* __restrict__ out0, float* __restrict__ out1)
{
    int gt = blockIdx.x*blockDim.x + threadIdx.x;
    int v = gt >> 5, lane = gt & 31;
    if (v >= NN) return;
    float2 erv = *reinterpret_cast<const float2*>(&g_er[v*64 + lane*2]);
    float a0 = __ldg(&attn[lane*2]), a1 = __ldg(&attn[lane*2 + 1]);
    int p0 = g_rowptr[v], p1 = g_rowptr[v+1];
    float m = __int_as_float(0xff800000);  // -inf
    float den = 0.f, ac0 = 0.f, ac1 = 0.f;
    for (int p = p0; p < p1; p++) {
        int s = __ldg(&g_csr_src[p]);
        float2 elv = *reinterpret_cast<const float2*>(&g_el[s*64 + lane*2]);
        float t0 = elv.x + erv.x; t0 = (t0 > 0.f) ? t0 : 0.2f*t0;
        float t1 = elv.y + erv.y; t1 = (t1 > 0.f) ? t1 : 0.2f*t1;
        float sc = t0*a0 + t1*a1;
        #pragma unroll
        for (int off = 16; off > 0; off >>= 1) sc += __shfl_xor_sync(0xffffffffu, sc, off);
        float nm = fmaxf(m, sc);
        float scale = __expf(m - nm);
        float w = __expf(sc - nm);
        den = den*scale + w;
        ac0 = ac0*scale + w*elv.x;
        ac1 = ac1*scale + w*elv.y;
        m = nm;
    }
    float inv = 1.f / den;
    float o0 = ac0*inv, o1 = ac1*inv;
    o0 = (o0 > 0.f) ? o0 : expm1f(o0);
    o1 = (o1 > 0.f) ? o1 : expm1f(o1);
    float2 r = make_float2(o0, o1);
    *reinterpret_cast<float2*>(&out0[v*64 + lane*2]) = r;
    *reinterpret_cast<float2*>(&out1[v*64 + lane*2]) = r;
}

// ---------------- GGC message aggregation (CSR gather, no atomics) ----------------
__global__ void k_agg() {
    int gt = blockIdx.x*blockDim.x + threadIdx.x;
    int v = gt >> 5, lane = gt & 31;
    if (v >= NN) return;
    int p0 = g_rowptr[v], p1 = g_rowptr[v+1];
    float ax = 0.f, ay = 0.f;
    for (int p = p0; p < p1; p++) {
        int ts = __ldg(&g_csr_tsrc[p]);
        float2 t = *reinterpret_cast<const float2*>(&g_trans[ts*64 + lane*2]);
        ax += t.x; ay += t.y;
    }
    *reinterpret_cast<float2*>(&g_agg[v*64 + lane*2]) = make_float2(ax, ay);
}

// ---------------- fused GRU cell: gi=a@Wih^T+bih, gh=h@Whh^T+bhh, gates, h update ----------------
__global__ __launch_bounds__(256) void k_gru(
    const float* __restrict__ H,
    const float* __restrict__ Wih, const float* __restrict__ bih,
    const float* __restrict__ Whh, const float* __restrict__ bhh,
    float* __restrict__ Hout, int n)
{
    extern __shared__ float sm[];
    float* As = sm;                 // [64][68]  a[d][m]
    float* Hs = sm + 64*68;         // [64][68]  h[d][m]
    float* Wi = sm + 2*64*68;       // [64][196] Wih[d][o]
    float* Wh = Wi + 64*196;        // [64][196] Whh[d][o]
    int tid = threadIdx.x;
    int m0 = blockIdx.x * 64;
    #pragma unroll
    for (int k = 0; k < 16; k++) {
        int idx = tid + k*256; int m = idx >> 6, d = idx & 63; int row = m0 + m;
        As[d*68 + m] = (row < n) ? g_agg[row*64 + d] : 0.f;
        Hs[d*68 + m] = (row < n) ? H[row*64 + d]    : 0.f;
    }
    #pragma unroll
    for (int k = 0; k < 48; k++) {
        int idx = tid + k*256; int o = idx >> 6, d = idx & 63;
        Wi[d*196 + o] = Wih[o*64 + d];
        Wh[d*196 + o] = Whh[o*64 + d];
    }
    __syncthreads();
    int ty = tid >> 4, tx = tid & 15;
    int j0 = tx * 4;
    unsigned long long gi[4][3][2], gh[4][3][2];
    #pragma unroll
    for (int i = 0; i < 4; i++)
        #pragma unroll
        for (int s = 0; s < 3; s++) { gi[i][s][0]=0ull; gi[i][s][1]=0ull; gh[i][s][0]=0ull; gh[i][s][1]=0ull; }

    #pragma unroll 2
    for (int d = 0; d < 64; d++) {
        float4 av = *reinterpret_cast<const float4*>(&As[d*68 + ty*4]);
        float4 hv = *reinterpret_cast<const float4*>(&Hs[d*68 + ty*4]);
        ulonglong2 wi0 = *reinterpret_cast<const ulonglong2*>(&Wi[d*196 + j0]);
        ulonglong2 wi1 = *reinterpret_cast<const ulonglong2*>(&Wi[d*196 + 64 + j0]);
        ulonglong2 wi2 = *reinterpret_cast<const ulonglong2*>(&Wi[d*196 + 128 + j0]);
        ulonglong2 wh0 = *reinterpret_cast<const ulonglong2*>(&Wh[d*196 + j0]);
        ulonglong2 wh1 = *reinterpret_cast<const ulonglong2*>(&Wh[d*196 + 64 + j0]);
        ulonglong2 wh2 = *reinterpret_cast<const ulonglong2*>(&Wh[d*196 + 128 + j0]);
        float a[4] = {av.x, av.y, av.z, av.w};
        float h[4] = {hv.x, hv.y, hv.z, hv.w};
        #pragma unroll
        for (int i = 0; i < 4; i++) {
            unsigned long long am = pk2(a[i]), hm = pk2(h[i]);
            FFMA2(gi[i][0][0], am, wi0.x); FFMA2(gi[i][0][1], am, wi0.y);
            FFMA2(gi[i][1][0], am, wi1.x); FFMA2(gi[i][1][1], am, wi1.y);
            FFMA2(gi[i][2][0], am, wi2.x); FFMA2(gi[i][2][1], am, wi2.y);
            FFMA2(gh[i][0][0], hm, wh0.x); FFMA2(gh[i][0][1], hm, wh0.y);
            FFMA2(gh[i][1][0], hm, wh1.x); FFMA2(gh[i][1][1], hm, wh1.y);
            FFMA2(gh[i][2][0], hm, wh2.x); FFMA2(gh[i][2][1], hm, wh2.y);
        }
    }
    #pragma unroll
    for (int i = 0; i < 4; i++) {
        int row = m0 + ty*4 + i;
        if (row >= n) continue;
        #pragma unroll
        for (int pr = 0; pr < 2; pr++) {
            float2 ir2 = up2(gi[i][0][pr]), iz2 = up2(gi[i][1][pr]), ic2 = up2(gi[i][2][pr]);
            float2 hr2 = up2(gh[i][0][pr]), hz2 = up2(gh[i][1][pr]), hc2 = up2(gh[i][2][pr]);
            #pragma unroll
            for (int e = 0; e < 2; e++) {
                int j = j0 + 2*pr + e;
                float ir = (e ? ir2.y : ir2.x) + __ldg(&bih[j]);
                float iz = (e ? iz2.y : iz2.x) + __ldg(&bih[64 + j]);
                float ic = (e ? ic2.y : ic2.x) + __ldg(&bih[128 + j]);
                float hr = (e ? hr2.y : hr2.x) + __ldg(&bhh[j]);
                float hz = (e ? hz2.y : hz2.x) + __ldg(&bhh[64 + j]);
                float hc = (e ? hc2.y : hc2.x) + __ldg(&bhh[128 + j]);
                float r = 1.f / (1.f + __expf(-(ir + hr)));
                float z = 1.f / (1.f + __expf(-(iz + hz)));
                float c = tanhf(ic + r*hc);
                float ho = Hs[j*68 + ty*4 + i];
                Hout[row*64 + j] = (1.f - z)*c + z*ho;
            }
        }
    }
}

// ---------------- host pipeline ----------------
extern "C" void kernel_launch(void* const* d_in, const int* in_sizes, int n_in,
                              void* d_out, int out_size)
{
    const float* x   = (const float*)d_in[0];
    const int*   src = (const int*)d_in[1];
    const int*   dst = (const int*)d_in[2];
    const int*   ety = (const int*)d_in[3];
    float* out = (float*)d_out;

    cudaFuncSetAttribute(gemm_dual, cudaFuncAttributeMaxDynamicSharedMemorySize, 51200);
    cudaFuncSetAttribute(k_gru,     cudaFuncAttributeMaxDynamicSharedMemorySize, 135168);

    float *p_el, *p_er, *p_tr;
    cudaGetSymbolAddress((void**)&p_el, g_el);
    cudaGetSymbolAddress((void**)&p_er, g_er);
    cudaGetSymbolAddress((void**)&p_tr, g_trans);

    k_zero<<<(NN + 255)/256, 256>>>();
    k_deg <<<(EF + 255)/256, 256>>>(dst);
    k_scan<<<1, 1024>>>();
    k_fill<<<(EF + 255)/256, 256>>>(src, dst, ety);

    const int gblocks   = (NN + 63) / 64;
    const int edgBlocks = (NN*32 + 255) / 256;

    for (int l = 0; l < 2; l++) {
        const float* Wsrc = (const float*)d_in[4 + l*11 + 0];
        const float* bsrc = (const float*)d_in[4 + l*11 + 1];
        const float* Wdst = (const float*)d_in[4 + l*11 + 2];
        const float* bdst = (const float*)d_in[4 + l*11 + 3];
        const float* attn = (const float*)d_in[4 + l*11 + 4];
        const float* gW   = (const float*)d_in[4 + l*11 + 5];
        const float* gb   = (const float*)d_in[4 + l*11 + 6];
        const float* Wih  = (const float*)d_in[4 + l*11 + 7];
        const float* bih  = (const float*)d_in[4 + l*11 + 8];
        const float* Whh  = (const float*)d_in[4 + l*11 + 9];
        const float* bhh  = (const float*)d_in[4 + l*11 + 10];

        const float* xin = (l == 0) ? x : (out + 1*ND);   // layer1 input = ggc0 output
        float* gatOut = out + (2*l)*ND;
        float* hbuf   = out + (2*l + 1)*ND;

        // GATv2: el/er projections, then fused online edge-softmax + aggregate + ELU
        gemm_dual<<<gblocks, 256, 51200>>>(xin, Wsrc, bsrc, Wdst, bdst, p_el, p_er, NN);
        k_gat<<<edgBlocks, 256>>>(attn, gatOut, hbuf);

        // GatedGraphConv: 2 GRU propagation steps
        for (int step = 0; step < 2; step++) {
            gemm_dual<<<gblocks, 256, 51200>>>(hbuf, gW, gb, gW + 64*64, gb + 64,
                                               p_tr, p_tr + ND, NN);
            k_agg<<<edgBlocks, 256>>>();
            k_gru<<<gblocks, 256, 135168>>>(hbuf, Wih, bih, Whh, bhh, hbuf, NN);
        }
    }
}

// round 2
// speedup vs baseline: 1.0035x; 1.0035x over previous
#include <cuda_runtime.h>
#include <cmath>

#define NN 50000
#define EE 800000
#define EF 850000          // EE + NN self loops
#define ND (NN*64)

// ---------------- scratch (device globals; no allocation) ----------------
__device__ int   g_deg[NN];
__device__ int   g_rowptr[NN+1];
__device__ int   g_cursor[NN];
__device__ int   g_csr_src[EF];     // src node per CSR slot
__device__ int   g_csr_tsrc[EF];    // etype*NN + src per CSR slot
__device__ float g_el[ND];
__device__ float g_er[ND];
__device__ float g_trans[2*ND];
__device__ float g_agg[ND];

// ---------------- packed f32x2 helpers ----------------
__device__ __forceinline__ unsigned long long pk2(float x) {
    unsigned long long r;
    asm("mov.b64 %0, {%1, %1};" : "=l"(r) : "r"(__float_as_uint(x)));
    return r;
}
__device__ __forceinline__ float2 up2(unsigned long long v) {
    float2 f;
    asm("mov.b64 {%0, %1}, %2;" : "=f"(f.x), "=f"(f.y) : "l"(v));
    return f;
}
#define FFMA2(c,a,b) asm("fma.rn.f32x2 %0, %1, %2, %0;" : "+l"(c) : "l"(a), "l"(b))

// ---------------- CSR build ----------------
__global__ void k_zero() {
    int i = blockIdx.x*blockDim.x + threadIdx.x;
    if (i < NN) g_deg[i] = 0;
}
__global__ void k_deg(const int* __restrict__ dst) {
    int e = blockIdx.x*blockDim.x + threadIdx.x;
    if (e >= EF) return;
    int d = (e < EE) ? dst[e] : (e - EE);
    atomicAdd(&g_deg[d], 1);
}
__global__ void k_scan() {
    __shared__ int part[1024];
    int t = threadIdx.x;
    const int CH = (NN + 1023) / 1024;   // 49
    int base = t * CH;
    int s = 0;
    for (int i = 0; i < CH; i++) { int idx = base + i; if (idx < NN) s += g_deg[idx]; }
    part[t] = s; __syncthreads();
    for (int off = 1; off < 1024; off <<= 1) {
        int v = (t >= off) ? part[t - off] : 0;
        __syncthreads();
        part[t] += v;
        __syncthreads();
    }
    int run = (t == 0) ? 0 : part[t-1];
    for (int i = 0; i < CH; i++) {
        int idx = base + i;
        if (idx < NN) { g_rowptr[idx] = run; g_cursor[idx] = run; run += g_deg[idx]; }
    }
    if (t == 1023) g_rowptr[NN] = run;
}
__global__ void k_fill(const int* __restrict__ src, const int* __restrict__ dst,
                       const int* __restrict__ ety) {
    int e = blockIdx.x*blockDim.x + threadIdx.x;
    if (e >= EF) return;
    int s = (e < EE) ? src[e] : (e - EE);
    int d = (e < EE) ? dst[e] : (e - EE);
    int t = ety[e];
    int pos = atomicAdd(&g_cursor[d], 1);
    g_csr_src[pos]  = s;
    g_csr_tsrc[pos] = t*NN + s;
}

// ---------------- dual GEMM: C0 = A@W0^T+b0, C1 = A@W1^T+b1 (64x64 each) ----------------
// block = 64 rows, 256 threads, f32x2 inner product, weights+tile in dyn smem (50KB)
__global__ __launch_bounds__(256) void gemm_dual(
    const float* __restrict__ A,
    const float* __restrict__ W0, const float* __restrict__ b0,
    const float* __restrict__ W1, const float* __restrict__ b1,
    float* __restrict__ C0, float* __restrict__ C1, int n)
{
    extern __shared__ float sm[];
    float* Xs = sm;             // [64][68]  Xs[d][m]
    float* Ws = sm + 64*68;     // [64][132] Ws[d][o], o in [0,128)
    int tid = threadIdx.x;
    int m0 = blockIdx.x * 64;
    #pragma unroll
    for (int k = 0; k < 16; k++) {
        int idx = tid + k*256; int m = idx >> 6, d = idx & 63; int row = m0 + m;
        Xs[d*68 + m] = (row < n) ? A[row*64 + d] : 0.f;
    }
    #pragma unroll
    for (int k = 0; k < 32; k++) {
        int idx = tid + k*256; int o = idx >> 6, d = idx & 63;
        Ws[d*132 + o] = (o < 64) ? W0[o*64 + d] : W1[(o-64)*64 + d];
    }
    __syncthreads();
    int ty = tid >> 4, tx = tid & 15;
    unsigned long long acc[4][4];
    #pragma unroll
    for (int i = 0; i < 4; i++)
        #pragma unroll
        for (int p = 0; p < 4; p++) acc[i][p] = 0ull;

    #pragma unroll 8
    for (int d = 0; d < 64; d++) {
        float4 av = *reinterpret_cast<const float4*>(&Xs[d*68 + ty*4]);
        ulonglong2 bA = *reinterpret_cast<const ulonglong2*>(&Ws[d*132 + tx*8]);
        ulonglong2 bB = *reinterpret_cast<const ulonglong2*>(&Ws[d*132 + tx*8 + 4]);
        unsigned long long a0 = pk2(av.x), a1 = pk2(av.y), a2 = pk2(av.z), a3 = pk2(av.w);
        FFMA2(acc[0][0],a0,bA.x); FFMA2(acc[0][1],a0,bA.y); FFMA2(acc[0][2],a0,bB.x); FFMA2(acc[0][3],a0,bB.y);
        FFMA2(acc[1][0],a1,bA.x); FFMA2(acc[1][1],a1,bA.y); FFMA2(acc[1][2],a1,bB.x); FFMA2(acc[1][3],a1,bB.y);
        FFMA2(acc[2][0],a2,bA.x); FFMA2(acc[2][1],a2,bA.y); FFMA2(acc[2][2],a2,bB.x); FFMA2(acc[2][3],a2,bB.y);
        FFMA2(acc[3][0],a3,bA.x); FFMA2(acc[3][1],a3,bA.y); FFMA2(acc[3][2],a3,bB.x); FFMA2(acc[3][3],a3,bB.y);
    }
    const float* bb; float* Cb; int ob = tx*8;
    if (tx < 8) { Cb = C0; bb = b0; } else { Cb = C1; bb = b1; ob -= 64; }
    #pragma unroll
    for (int i = 0; i < 4; i++) {
        int row = m0 + ty*4 + i;
        if (row >= n) continue;
        #pragma unroll
        for (int p = 0; p < 4; p++) {
            float2 v = up2(acc[i][p]);
            int o = ob + 2*p;
            v.x += bb[o]; v.y += bb[o+1];
            *reinterpret_cast<float2*>(&Cb[row*64 + o]) = v;
        }
    }
}

// ---------------- fused GATv2 edge-softmax + aggregation (online softmax) ----------------
__global__ void k_gat(const float* __restrict__ attn,
                      float* __restrict__ out0, float* __restrict__ out1)
{
    int gt = blockIdx.x*blockDim.x + threadIdx.x;
    int v = gt >> 5, lane = gt & 31;
    if (v >= NN) return;
    float2 erv = *reinterpret_cast<const float2*>(&g_er[v*64 + lane*2]);
    float a0 = __ldg(&attn[lane*2]), a1 = __ldg(&attn[lane*2 + 1]);
    int p0 = g_rowptr[v], p1 = g_rowptr[v+1];
    float m = __int_as_float(0xff800000);  // -inf
    float den = 0.f, ac0 = 0.f, ac1 = 0.f;
    for (int p = p0; p < p1; p++) {
        int s = __ldg(&g_csr_src[p]);
        float2 elv = *reinterpret_cast<const float2*>(&g_el[s*64 + lane*2]);
        float t0 = elv.x + erv.x; t0 = (t0 > 0.f) ? t0 : 0.2f*t0;
        float t1 = elv.y + erv.y; t1 = (t1 > 0.f) ? t1 : 0.2f*t1;
        float sc = t0*a0 + t1*a1;
        #pragma unroll
        for (int off = 16; off > 0; off >>= 1) sc += __shfl_xor_sync(0xffffffffu, sc, off);
        float nm = fmaxf(m, sc);
        float scale = __expf(m - nm);
        float w = __expf(sc - nm);
        den = den*scale + w;
        ac0 = ac0*scale + w*elv.x;
        ac1 = ac1*scale + w*elv.y;
        m = nm;
    }
    float inv = 1.f / den;
    float o0 = ac0*inv, o1 = ac1*inv;
    o0 = (o0 > 0.f) ? o0 : expm1f(o0);
    o1 = (o1 > 0.f) ? o1 : expm1f(o1);
    float2 r = make_float2(o0, o1);
    *reinterpret_cast<float2*>(&out0[v*64 + lane*2]) = r;
    *reinterpret_cast<float2*>(&out1[v*64 + lane*2]) = r;
}

// ---------------- GGC message aggregation (CSR gather, no atomics) ----------------
__global__ void k_agg() {
    int gt = blockIdx.x*blockDim.x + threadIdx.x;
    int v = gt >> 5, lane = gt & 31;
    if (v >= NN) return;
    int p0 = g_rowptr[v], p1 = g_rowptr[v+1];
    float ax = 0.f, ay = 0.f;
    for (int p = p0; p < p1; p++) {
        int ts = __ldg(&g_csr_tsrc[p]);
        float2 t = *reinterpret_cast<const float2*>(&g_trans[ts*64 + lane*2]);
        ax += t.x; ay += t.y;
    }
    *reinterpret_cast<float2*>(&g_agg[v*64 + lane*2]) = make_float2(ax, ay);
}

// ---------------- fused GRU cell: gi=a@Wih^T+bih, gh=h@Whh^T+bhh, gates, h update ----------------
__global__ __launch_bounds__(256) void k_gru(
    const float* __restrict__ H,
    const float* __restrict__ Wih, const float* __restrict__ bih,
    const float* __restrict__ Whh, const float* __restrict__ bhh,
    float* __restrict__ Hout, int n)
{
    extern __shared__ float sm[];
    float* As = sm;                 // [64][68]  a[d][m]
    float* Hs = sm + 64*68;         // [64][68]  h[d][m]
    float* Wi = sm + 2*64*68;       // [64][196] Wih[d][o]
    float* Wh = Wi + 64*196;        // [64][196] Whh[d][o]
    int tid = threadIdx.x;
    int m0 = blockIdx.x * 64;
    #pragma unroll
    for (int k = 0; k < 16; k++) {
        int idx = tid + k*256; int m = idx >> 6, d = idx & 63; int row = m0 + m;
        As[d*68 + m] = (row < n) ? g_agg[row*64 + d] : 0.f;
        Hs[d*68 + m] = (row < n) ? H[row*64 + d]    : 0.f;
    }
    #pragma unroll
    for (int k = 0; k < 48; k++) {
        int idx = tid + k*256; int o = idx >> 6, d = idx & 63;
        Wi[d*196 + o] = Wih[o*64 + d];
        Wh[d*196 + o] = Whh[o*64 + d];
    }
    __syncthreads();
    int ty = tid >> 4, tx = tid & 15;
    int j0 = tx * 4;
    unsigned long long gi[4][3][2], gh[4][3][2];
    #pragma unroll
    for (int i = 0; i < 4; i++)
        #pragma unroll
        for (int s = 0; s < 3; s++) { gi[i][s][0]=0ull; gi[i][s][1]=0ull; gh[i][s][0]=0ull; gh[i][s][1]=0ull; }

    #pragma unroll 2
    for (int d = 0; d < 64; d++) {
        float4 av = *reinterpret_cast<const float4*>(&As[d*68 + ty*4]);
        float4 hv = *reinterpret_cast<const float4*>(&Hs[d*68 + ty*4]);
        ulonglong2 wi0 = *reinterpret_cast<const ulonglong2*>(&Wi[d*196 + j0]);
        ulonglong2 wi1 = *reinterpret_cast<const ulonglong2*>(&Wi[d*196 + 64 + j0]);
        ulonglong2 wi2 = *reinterpret_cast<const ulonglong2*>(&Wi[d*196 + 128 + j0]);
        ulonglong2 wh0 = *reinterpret_cast<const ulonglong2*>(&Wh[d*196 + j0]);
        ulonglong2 wh1 = *reinterpret_cast<const ulonglong2*>(&Wh[d*196 + 64 + j0]);
        ulonglong2 wh2 = *reinterpret_cast<const ulonglong2*>(&Wh[d*196 + 128 + j0]);
        float a[4] = {av.x, av.y, av.z, av.w};
        float h[4] = {hv.x, hv.y, hv.z, hv.w};
        #pragma unroll
        for (int i = 0; i < 4; i++) {
            unsigned long long am = pk2(a[i]), hm = pk2(h[i]);
            FFMA2(gi[i][0][0], am, wi0.x); FFMA2(gi[i][0][1], am, wi0.y);
            FFMA2(gi[i][1][0], am, wi1.x); FFMA2(gi[i][1][1], am, wi1.y);
            FFMA2(gi[i][2][0], am, wi2.x); FFMA2(gi[i][2][1], am, wi2.y);
            FFMA2(gh[i][0][0], hm, wh0.x); FFMA2(gh[i][0][1], hm, wh0.y);
            FFMA2(gh[i][1][0], hm, wh1.x); FFMA2(gh[i][1][1], hm, wh1.y);
            FFMA2(gh[i][2][0], hm, wh2.x); FFMA2(gh[i][2][1], hm, wh2.y);
        }
    }
    #pragma unroll
    for (int i = 0; i < 4; i++) {
        int row = m0 + ty*4 + i;
        if (row >= n) continue;
        #pragma unroll
        for (int pr = 0; pr < 2; pr++) {
            float2 ir2 = up2(gi[i][0][pr]), iz2 = up2(gi[i][1][pr]), ic2 = up2(gi[i][2][pr]);
            float2 hr2 = up2(gh[i][0][pr]), hz2 = up2(gh[i][1][pr]), hc2 = up2(gh[i][2][pr]);
            #pragma unroll
            for (int e = 0; e < 2; e++) {
                int j = j0 + 2*pr + e;
                float ir = (e ? ir2.y : ir2.x) + __ldg(&bih[j]);
                float iz = (e ? iz2.y : iz2.x) + __ldg(&bih[64 + j]);
                float ic = (e ? ic2.y : ic2.x) + __ldg(&bih[128 + j]);
                float hr = (e ? hr2.y : hr2.x) + __ldg(&bhh[j]);
                float hz = (e ? hz2.y : hz2.x) + __ldg(&bhh[64 + j]);
                float hc = (e ? hc2.y : hc2.x) + __ldg(&bhh[128 + j]);
                float r = 1.f / (1.f + __expf(-(ir + hr)));
                float z = 1.f / (1.f + __expf(-(iz + hz)));
                float c = tanhf(ic + r*hc);
                float ho = Hs[j*68 + ty*4 + i];
                Hout[row*64 + j] = (1.f - z)*c + z*ho;
            }
        }
    }
}

// ---------------- host pipeline ----------------
extern "C" void kernel_launch(void* const* d_in, const int* in_sizes, int n_in,
                              void* d_out, int out_size)
{
    const float* x   = (const float*)d_in[0];
    const int*   src = (const int*)d_in[1];
    const int*   dst = (const int*)d_in[2];
    const int*   ety = (const int*)d_in[3];
    float* out = (float*)d_out;

    cudaFuncSetAttribute(gemm_dual, cudaFuncAttributeMaxDynamicSharedMemorySize, 51200);
    cudaFuncSetAttribute(k_gru,     cudaFuncAttributeMaxDynamicSharedMemorySize, 135168);

    float *p_el, *p_er, *p_tr;
    cudaGetSymbolAddress((void**)&p_el, g_el);
    cudaGetSymbolAddress((void**)&p_er, g_er);
    cudaGetSymbolAddress((void**)&p_tr, g_trans);

    k_zero<<<(NN + 255)/256, 256>>>();
    k_deg <<<(EF + 255)/256, 256>>>(dst);
    k_scan<<<1, 1024>>>();
    k_fill<<<(EF + 255)/256, 256>>>(src, dst, ety);

    const int gblocks   = (NN + 63) / 64;
    const int edgBlocks = (NN*32 + 255) / 256;

    for (int l = 0; l < 2; l++) {
        const float* Wsrc = (const float*)d_in[4 + l*11 + 0];
        const float* bsrc = (const float*)d_in[4 + l*11 + 1];
        const float* Wdst = (const float*)d_in[4 + l*11 + 2];
        const float* bdst = (const float*)d_in[4 + l*11 + 3];
        const float* attn = (const float*)d_in[4 + l*11 + 4];
        const float* gW   = (const float*)d_in[4 + l*11 + 5];
        const float* gb   = (const float*)d_in[4 + l*11 + 6];
        const float* Wih  = (const float*)d_in[4 + l*11 + 7];
        const float* bih  = (const float*)d_in[4 + l*11 + 8];
        const float* Whh  = (const float*)d_in[4 + l*11 + 9];
        const float* bhh  = (const float*)d_in[4 + l*11 + 10];

        const float* xin = (l == 0) ? x : (out + 1*ND);   // layer1 input = ggc0 output
        float* gatOut = out + (2*l)*ND;
        float* hbuf   = out + (2*l + 1)*ND;

        // GATv2: el/er projections, then fused online edge-softmax + aggregate + ELU
        gemm_dual<<<gblocks, 256, 51200>>>(xin, Wsrc, bsrc, Wdst, bdst, p_el, p_er, NN);
        k_gat<<<edgBlocks, 256>>>(attn, gatOut, hbuf);

        // GatedGraphConv: 2 GRU propagation steps
        for (int step = 0; step < 2; step++) {
            gemm_dual<<<gblocks, 256, 51200>>>(hbuf, gW, gb, gW + 64*64, gb + 64,
                                               p_tr, p_tr + ND, NN);
            k_agg<<<edgBlocks, 256>>>();
            k_gru<<<gblocks, 256, 135168>>>(hbuf, Wih, bih, Whh, bhh, hbuf, NN);
        }
    }
}